// round 12
// baseline (speedup 1.0000x reference)
#include <cuda_runtime.h>
#include <stdint.h>

// Problem constants
#define BATCH        8
#define DOF          300000
#define NFIX         3000
#define NEWTON_ITERS 6
#define D4           (DOF / 4)            // 75000 float4 per batch row
#define BX           19                   // blocks per batch row
#define TPB          1024
#define STRIDE       (BX * TPB)           // 19456 float4-threads per batch row
#define CHUNKS       4                    // 4*19456 = 77824 >= 75000
#define D4P          (CHUNKS * STRIDE)    // padded float4 per batch row
#define NMON         6                    // GG, PP, QQ, (-GP), (-GQ), PQ
#define NP2          (2 * CHUNKS)         // 8 packed f32x2 values per thread
#define NWARP        (TPB / 32)

// Grid = 152 blocks = one per GB300 SM, 1024 thr, 64 regs -> all co-resident.

// alphas[t] = max(0.5^t, 0.05); index 5 == ALPHA_MIN
__constant__ float c_alpha[16] = {1.0f, 0.5f, 0.25f, 0.125f, 0.0625f, 0.05f, 0.05f, 0.05f,
                                  0.05f, 0.05f, 0.05f, 0.05f, 0.05f, 0.05f, 0.05f, 0.05f};

#define C04 0x3ECCCCCD3ECCCCCDull   // (0.4f, 0.4f)
#define C12 0x3F99999A3F99999Aull   // (1.2f, 1.2f)

// Device scratch (allocation-free).
// g_fm: packed (-f) masked to 0 at fixed/tail slots, per batch; g_km: packed k
// masked to 1 (dup writes across batches identical -> benign). Each block
// writes/reads only its own slice -> no inter-block sync needed; replay
// rewrites are identical.
__device__ ulonglong2 g_fm[BATCH * D4P];
__device__ ulonglong2 g_km[D4P];
// g_sum: 3-buffer rotation. Iteration it accumulates into buf it%3. The
// last-arriving block of iteration it zeroes buf (it+2)%3 BEFORE its release
// mailbox write; writers of that buffer (iteration it+2) only start after
// acquiring mailbox it+1 > it, and its previous readers finished before
// mailbox it-1 -> race-free. Replay: buffers left zeroed except buf2, which
// the next launch's it=0 last-arriver zeroes before any it=2 accumulation.
// g_cnt: one monotone counter per batch (target BX*(it+1)); reset to 0 by the
// it=5 last-arriver (nobody polls the counter; only atomics touch it).
// g_mb: per-batch mailbox ((it+1)<<4 | alpha_idx). Stale value from previous
// replay has tag 6; polls compare exact tag it+1 in 1..6, and single-address
// coherence (each block observed tag it before polling it+1) prevents
// confusing the stale tag-6 word with the fresh one.
__device__ float        g_sum[3][NMON * BATCH];
__device__ int          g_cnt[BATCH];
__device__ unsigned     g_mb[BATCH];

// ---- packed f32x2 helpers ---------------------------------------------------
__device__ __forceinline__ uint64_t fma2(uint64_t a, uint64_t b, uint64_t c)
{
    uint64_t d;
    asm("fma.rn.f32x2 %0, %1, %2, %3;" : "=l"(d) : "l"(a), "l"(b), "l"(c));
    return d;
}
__device__ __forceinline__ uint64_t mul2(uint64_t a, uint64_t b)
{
    uint64_t d;
    asm("mul.rn.f32x2 %0, %1, %2;" : "=l"(d) : "l"(a), "l"(b));
    return d;
}
__device__ __forceinline__ uint64_t pack2(float lo, float hi)
{
    uint64_t d;
    asm("mov.b64 %0, {%1, %2};" : "=l"(d) : "f"(lo), "f"(hi));
    return d;
}
__device__ __forceinline__ void unpack2(uint64_t v, float& lo, float& hi)
{
    asm("mov.b64 {%0, %1}, %2;" : "=f"(lo), "=f"(hi) : "l"(v));
}
__device__ __forceinline__ uint64_t rcp2(uint64_t h)
{
    float lo, hi;
    unpack2(h, lo, hi);
    float rl, rh;
    asm("rcp.approx.f32 %0, %1;" : "=f"(rl) : "f"(lo));
    asm("rcp.approx.f32 %0, %1;" : "=f"(rh) : "f"(hi));
    return pack2(rl, rh);
}
// ---- sync helpers -------------------------------------------------------------
__device__ __forceinline__ void redAddRelaxedF32(float* a, float v)
{
    asm volatile("red.relaxed.gpu.global.add.f32 [%0], %1;" :: "l"(a), "f"(v) : "memory");
}
__device__ __forceinline__ int atomAddAcqRel(int* a, int v)
{
    int old;
    asm volatile("atom.acq_rel.gpu.global.add.s32 %0, [%1], %2;"
                 : "=r"(old) : "l"(a), "r"(v) : "memory");
    return old;
}
__device__ __forceinline__ void stReleaseU32(unsigned* a, unsigned v)
{
    asm volatile("st.release.gpu.global.u32 [%0], %1;" :: "l"(a), "r"(v) : "memory");
}
__device__ __forceinline__ unsigned ldAcquireU32(const unsigned* a)
{
    unsigned v;
    asm volatile("ld.acquire.gpu.global.u32 %0, [%1];" : "=r"(v) : "l"(a) : "memory");
    return v;
}

// ---------------------------------------------------------------------------
// Per-pair hot math (packed f32x2; inputs pre-masked/negated => no mask ops):
//   g' = u*(k+0.4u^2) - f  (= -g);  h = k + 1.2u^2;  du = g'*rcp(h) (= -g/h)
//   P = u*du^2; Q = du^3; acc: GG, PP, QQ, -GP, -GQ, PQ
__device__ __forceinline__ void mathPair(uint64_t u, uint64_t fneg, uint64_t k,
                                         uint64_t* duslot, uint64_t acc[NMON])
{
    uint64_t u2 = mul2(u, u);
    uint64_t t  = fma2(C04, u2, k);
    uint64_t h  = fma2(C12, u2, k);
    uint64_t gp = fma2(u, t, fneg);
    uint64_t r  = rcp2(h);
    uint64_t v  = mul2(gp, r);
    *duslot = v;
    uint64_t v2 = mul2(v, v);
    uint64_t P  = mul2(u, v2);
    uint64_t Q  = mul2(v, v2);
    acc[0] = fma2(gp, gp, acc[0]);
    acc[1] = fma2(P,  P,  acc[1]);
    acc[2] = fma2(Q,  Q,  acc[2]);
    acc[3] = fma2(gp, P,  acc[3]);
    acc[4] = fma2(gp, Q,  acc[4]);
    acc[5] = fma2(P,  Q,  acc[5]);
}

// ---------------------------------------------------------------------------
__global__ void __launch_bounds__(TPB, 1)
kSolve(const float* __restrict__ f,
       const float* __restrict__ u0,
       const float* __restrict__ kd,
       const int*   __restrict__ fixed_dofs,
       float* __restrict__ out)
{
    const int tid  = threadIdx.x;
    const int lane = tid & 31;
    const int wid  = tid >> 5;
    const int bx   = blockIdx.x;
    const int b    = blockIdx.y;
    const int i0   = bx * TPB + tid;

    const float4* f4 = reinterpret_cast<const float4*>(f) + (size_t)b * D4;
    const float4* k4 = reinterpret_cast<const float4*>(kd);
    const float4* u4 = reinterpret_cast<const float4*>(u0) + (size_t)b * D4;

    // dynamic shared memory partition
    extern __shared__ char smraw[];
    uint64_t* du_s  = reinterpret_cast<uint64_t*>(smraw);                    // 64 KB
    uint32_t* maskw = reinterpret_cast<uint32_t*>(smraw + NP2 * TPB * 8);    // 512 words
    float*    sred  = reinterpret_cast<float*>(maskw + CHUNKS * (TPB / 8));  // 2*NWARP*NMON

    // ---- build this block's fixed-dof bitmap (once) ----
    for (int j = tid; j < CHUNKS * (TPB / 8); j += TPB) maskw[j] = 0u;
    __syncthreads();
    for (int j = tid; j < NFIX; j += TPB) {
        int d = fixed_dofs[j];
#pragma unroll
        for (int c = 0; c < CHUNKS; c++) {
            int lo = (bx * TPB + c * STRIDE) * 4;
            unsigned off = (unsigned)(d - lo);
            if (off < (unsigned)(TPB * 4))
                atomicOr(&maskw[c * (TPB / 8) + (off >> 5)], 1u << (off & 31));
        }
    }
    __syncthreads();

    // ---- setup: masked u -> registers; (-f,k) masked -> padded scratch ----
    uint32_t nibs = 0;
    uint64_t up[NP2];
#pragma unroll
    for (int c = 0; c < CHUNKS; c++) {
        int i  = i0 + c * STRIDE;
        int ic = (i < D4) ? i : (D4 - 1);
        float4 uu = u4[ic];
        float4 ff = f4[ic];
        float4 kk = k4[ic];
        uint32_t w  = maskw[c * (TPB / 8) + (tid >> 3)];
        uint32_t nb = (w >> ((tid & 7) * 4)) & 0xFu;
        if (i >= D4) nb = 0xFu;
        nibs |= nb << (c * 4);

        float ua[4] = {uu.x, uu.y, uu.z, uu.w};
        float fa[4] = {ff.x, ff.y, ff.z, ff.w};
        float ka[4] = {kk.x, kk.y, kk.z, kk.w};
        float ul[4], fm[4], km[4];
#pragma unroll
        for (int j = 0; j < 4; j++) {
            bool fx = (nb >> j) & 1u;
            ul[j] = fx ? 0.0f : ua[j];
            fm[j] = fx ? 0.0f : -fa[j];
            km[j] = fx ? 1.0f : ka[j];
        }
        up[2 * c + 0] = pack2(ul[0], ul[1]);
        up[2 * c + 1] = pack2(ul[2], ul[3]);
        ulonglong2 pf; pf.x = pack2(fm[0], fm[1]); pf.y = pack2(fm[2], fm[3]);
        ulonglong2 pk; pk.x = pack2(km[0], km[1]); pk.y = pack2(km[2], km[3]);
        g_fm[(size_t)b * D4P + i] = pf;
        g_km[i] = pk;
    }

    for (int it = 0; it < NEWTON_ITERS; it++) {
        uint64_t acc[NMON];
#pragma unroll
        for (int m = 0; m < NMON; m++) acc[m] = 0ull;

        // ---- compute phase: packed f32x2; du -> own smem column ----
#pragma unroll
        for (int c = 0; c < CHUNKS; c++) {
            int i = i0 + c * STRIDE;
            ulonglong2 fp = g_fm[(size_t)b * D4P + i];
            ulonglong2 kp = g_km[i];
            mathPair(up[2 * c + 0], fp.x, kp.x, &du_s[(2 * c + 0) * TPB + tid], acc);
            mathPair(up[2 * c + 1], fp.y, kp.y, &du_s[(2 * c + 1) * TPB + tid], acc);
        }

        // ---- warp-level reduce, stage per-warp sums (parity buffered) ----
        const int par = it & 1;
        float sa[NMON];
#pragma unroll
        for (int m = 0; m < NMON; m++) {
            float lo, hi; unpack2(acc[m], lo, hi);
            sa[m] = lo + hi;
#pragma unroll
            for (int o = 16; o; o >>= 1)
                sa[m] += __shfl_down_sync(0xffffffffu, sa[m], o);
        }
        if (lane == 0) {
#pragma unroll
            for (int m = 0; m < NMON; m++)
                sred[(par * NWARP + wid) * NMON + m] = sa[m];
        }
        __syncthreads();   // the ONLY block-wide sync per iteration

        const int buf = it % 3;
        // ---- warp 0: cross-warp reduce + global arrival (lane 0 only) ----
        if (wid == 0) {
            float s[NMON];
#pragma unroll
            for (int m = 0; m < NMON; m++)
                s[m] = sred[(par * NWARP + lane) * NMON + m];
#pragma unroll
            for (int o = 16; o; o >>= 1) {
#pragma unroll
                for (int m = 0; m < NMON; m++)
                    s[m] += __shfl_down_sync(0xffffffffu, s[m], o);
            }
            if (lane == 0) {
#pragma unroll
                for (int m = 0; m < NMON; m++)
                    redAddRelaxedF32(&g_sum[buf][m * BATCH + b], s[m]);
                int old = atomAddAcqRel(&g_cnt[b], 1);
                if (old == BX * (it + 1) - 1) {
                    // last arriver: zero buf it+2 (race-free, see header),
                    // read sums, pick alpha, publish mailbox.
                    float* z = &g_sum[(it + 2) % 3][0];
#pragma unroll
                    for (int m = 0; m < NMON; m++) __stcg(&z[m * BATCH + b], 0.0f);
                    const float* S = &g_sum[buf][0];
                    float gg  = __ldcg(&S[0 * BATCH + b]);
                    float pp  = __ldcg(&S[1 * BATCH + b]);
                    float qq  = __ldcg(&S[2 * BATCH + b]);
                    float gpn = __ldcg(&S[3 * BATCH + b]);   // -GP
                    float gqn = __ldcg(&S[4 * BATCH + b]);   // -GQ
                    float pq  = __ldcg(&S[5 * BATCH + b]);
                    unsigned aidx = 5;                        // ALPHA_MIN
#pragma unroll
                    for (int tr = 7; tr >= 0; tr--) {
                        float at = c_alpha[tr];
                        float c1 = 1.0f + at;
                        float c2 = -1.2f * at * at;
                        float c3 = -0.4f * at * at * at;
                        float n2 = c1 * c1 * gg + c2 * c2 * pp + c3 * c3 * qq
                                 + 2.0f * (-c1 * c2 * gpn - c1 * c3 * gqn + c2 * c3 * pq);
                        if (n2 < gg) aidx = (unsigned)tr;
                    }
                    if (it == NEWTON_ITERS - 1) __stcg(&g_cnt[b], 0);  // replay reset
                    stReleaseU32(&g_mb[b], ((unsigned)(it + 1) << 4) | aidx);
                }
            }
        }

        // ---- every warp polls the mailbox independently ----
        unsigned expect = (unsigned)(it + 1) << 4;
        unsigned mb = ldAcquireU32(&g_mb[b]);
        while ((mb & 0xFFFFFFF0u) != expect) {
            __nanosleep(32);
            mb = ldAcquireU32(&g_mb[b]);
        }
        float a = c_alpha[mb & 15u];

        // ---- update: u += alpha * du (own smem column; no block sync) ----
        uint64_t A2 = pack2(a, a);
#pragma unroll
        for (int x = 0; x < NP2; x++)
            up[x] = fma2(A2, du_s[x * TPB + tid], up[x]);
    }

    // ---- final store: restore u0 at fixed lanes, skip padded tails ----
    float4* o4 = reinterpret_cast<float4*>(out) + (size_t)b * D4;
#pragma unroll
    for (int c = 0; c < CHUNKS; c++) {
        int i = i0 + c * STRIDE;
        if (i < D4) {
            uint32_t nb = (nibs >> (c * 4)) & 0xFu;
            float4 uu = u4[i];
            float r0, r1, r2, r3;
            unpack2(up[2 * c + 0], r0, r1);
            unpack2(up[2 * c + 1], r2, r3);
            float4 o;
            o.x = (nb & 1u) ? uu.x : r0;
            o.y = (nb & 2u) ? uu.y : r1;
            o.z = (nb & 4u) ? uu.z : r2;
            o.w = (nb & 8u) ? uu.w : r3;
            o4[i] = o;
        }
    }
}

// ---------------------------------------------------------------------------
extern "C" void kernel_launch(void* const* d_in, const int* in_sizes, int n_in,
                              void* d_out, int out_size)
{
    const float* f  = (const float*)d_in[0];   // external_forces [B, DOF]
    const float* u0 = (const float*)d_in[1];   // u0              [B, DOF]
    const float* kd = (const float*)d_in[2];   // k_diag          [DOF]
    const int*   fd = (const int*)d_in[3];     // fixed_dofs      [NFIX]

    const size_t smem = (size_t)NP2 * TPB * 8                 // du_s (64KB)
                      + (size_t)CHUNKS * (TPB / 8) * 4        // maskw
                      + (size_t)2 * NWARP * NMON * 4          // sred (parity)
                      + 16;
    static int configured = 0;
    if (!configured) {
        cudaFuncSetAttribute(kSolve, cudaFuncAttributeMaxDynamicSharedMemorySize,
                             (int)smem);
        configured = 1;
    }
    kSolve<<<dim3(BX, BATCH), TPB, smem>>>(f, u0, kd, fd, (float*)d_out);
}

// round 13
// speedup vs baseline: 1.8065x; 1.8065x over previous
#include <cuda_runtime.h>
#include <stdint.h>

// Problem constants
#define BATCH        8
#define DOF          300000
#define NFIX         3000
#define NEWTON_ITERS 6
#define D4           (DOF / 4)            // 75000 float4 per batch row
#define BX           19                   // blocks per batch row
#define TPB          1024
#define STRIDE       (BX * TPB)           // 19456 float4-threads per batch row
#define CHUNKS       4                    // 4*19456 = 77824 >= 75000
#define NMON         6                    // GG, PP, QQ, GP, GQ, PQ
#define NV           (4 * CHUNKS)         // 16 values per thread
#define NWARP        (TPB / 32)

// Grid = 152 blocks = one per GB300 SM, 1024 threads, launch_bounds(1024,1):
// all CTAs co-resident -> persistent spin barrier cannot deadlock.

// alphas[t] = max(0.5^t, 0.05)
__constant__ float c_alpha[8] = {1.0f, 0.5f, 0.25f, 0.125f, 0.0625f, 0.05f, 0.05f, 0.05f};

// Device globals (allocation-free scratch).
//
// g_sum: 3-buffer rotation; iteration it accumulates into buf it%3 via
// relaxed float red.add. After passing barrier it, bx0 zeroes buf (it+2)%3
// (its readers finished before barrier it); the zero is release-ordered by
// bx0's arrival at barrier it+1, before any block starts accumulating into
// it at iteration it+2. Replay: it=4 zeroes buf0, it=5 zeroes buf1, next
// launch's it=0 zeroes buf2 (first used at iteration 2). First launch: 0.
//
// g_cnt: deferred-reset counters (replay-safe): after passing barrier it,
// bx0 resets counter it-1 (provably unpolled); at it=0 it resets counter 5
// (stale from previous replay; arrivals at counter 5 require passing
// barriers 1..4 first, each ordered after the reset).
__device__ float g_sum[3][NMON * BATCH];
__device__ int   g_cnt[NEWTON_ITERS][BATCH];

__device__ __forceinline__ float frcp_approx(float x)
{
    float r;
    asm("rcp.approx.f32 %0, %1;" : "=f"(r) : "f"(x));
    return r;
}
__device__ __forceinline__ void redAddRelaxedF32(float* a, float v)
{
    asm volatile("red.relaxed.gpu.global.add.f32 [%0], %1;" :: "l"(a), "f"(v) : "memory");
}
__device__ __forceinline__ void redAddReleaseS32(int* a, int v)
{
    asm volatile("red.release.gpu.global.add.s32 [%0], %1;" :: "l"(a), "r"(v) : "memory");
}
__device__ __forceinline__ int ldAcquireS32(const int* a)
{
    int v;
    asm volatile("ld.acquire.gpu.global.s32 %0, [%1];" : "=r"(v) : "l"(a) : "memory");
    return v;
}

// ---------------------------------------------------------------------------
// Persistent Newton solver, single launch, ONE CTA PER SM.
//   g = free*(f - (k*u + 0.4u^3)); h = k + 1.2u^2; du = -g/h
//   monomials G=g, P=u*du^2, Q=du^3 -> 6 sums; trial residual is the exact
//   polynomial r(a) = (1+a)G - 1.2a^2 P - 0.4a^3 Q, so all 8 trial norms^2
//   are quadratic forms in the 6 sums (GG also = init norm^2).
//
//   f and k are pre-masked ONCE into shared memory (f->0, k->1, u->0 at
//   fixed/tail lanes), so the hot loop is LDS + FMA only: zero global
//   traffic, zero mask ALU -> minimal cross-SM arrival spread.
//
//   Sync per iteration: 1 syncthreads -> warp0 cross-warp shuffle reduce;
//   lane0: 6x red.add (relaxed), release-arrive, acquire-poll (ONE poller
//   per block), alpha, housekeeping -> 1 syncthreads -> all warps update.
__global__ void __launch_bounds__(TPB, 1)
kSolve(const float* __restrict__ f,
       const float* __restrict__ u0,
       const float* __restrict__ kd,
       const int*   __restrict__ fixed_dofs,
       float* __restrict__ out)
{
    const int tid  = threadIdx.x;
    const int lane = tid & 31;
    const int wid  = tid >> 5;
    const int bx   = blockIdx.x;
    const int b    = blockIdx.y;
    const int i0   = bx * TPB + tid;

    const float4* f4 = reinterpret_cast<const float4*>(f) + (size_t)b * D4;
    const float4* k4 = reinterpret_cast<const float4*>(kd);
    const float4* u4 = reinterpret_cast<const float4*>(u0) + (size_t)b * D4;

    // dynamic shared memory partition
    extern __shared__ char smraw[];
    float4*   sfm   = reinterpret_cast<float4*>(smraw);                   // 64 KB
    float4*   skm   = sfm + CHUNKS * TPB;                                 // 64 KB
    uint32_t* maskw = reinterpret_cast<uint32_t*>(skm + CHUNKS * TPB);    // 2 KB
    float*    sred  = reinterpret_cast<float*>(maskw + CHUNKS * (TPB/8)); // 768 B
    float*    s_alp = sred + NWARP * NMON;

    // ---- build this block's fixed-dof bitmap (once) ----
    for (int j = tid; j < CHUNKS * (TPB / 8); j += TPB) maskw[j] = 0u;
    __syncthreads();
    for (int j = tid; j < NFIX; j += TPB) {
        int d = fixed_dofs[j];
#pragma unroll
        for (int c = 0; c < CHUNKS; c++) {
            int lo = (bx * TPB + c * STRIDE) * 4;
            unsigned off = (unsigned)(d - lo);
            if (off < (unsigned)(TPB * 4))
                atomicOr(&maskw[c * (TPB / 8) + (off >> 5)], 1u << (off & 31));
        }
    }
    __syncthreads();

    // ---- setup: masked u -> registers; masked f,k -> shared memory ----
    uint32_t nibs = 0;
    float u[NV];
    float du[NV];
#pragma unroll
    for (int c = 0; c < CHUNKS; c++) {
        int i  = i0 + c * STRIDE;
        int ic = (i < D4) ? i : (D4 - 1);
        float4 uu = u4[ic];
        float4 ff = f4[ic];
        float4 kk = k4[ic];
        uint32_t w  = maskw[c * (TPB / 8) + (tid >> 3)];
        uint32_t nb = (w >> ((tid & 7) * 4)) & 0xFu;
        if (i >= D4) nb = 0xFu;
        nibs |= nb << (c * 4);

        float ua[4] = {uu.x, uu.y, uu.z, uu.w};
        float fa[4] = {ff.x, ff.y, ff.z, ff.w};
        float ka[4] = {kk.x, kk.y, kk.z, kk.w};
        float fm[4], km[4];
#pragma unroll
        for (int j = 0; j < 4; j++) {
            bool fx = (nb >> j) & 1u;
            u[c * 4 + j] = fx ? 0.0f : ua[j];   // u=0 at fixed -> g=0, du=0
            fm[j] = fx ? 0.0f : fa[j];
            km[j] = fx ? 1.0f : ka[j];
        }
        float4 pf = {fm[0], fm[1], fm[2], fm[3]};
        float4 pk = {km[0], km[1], km[2], km[3]};
        sfm[c * TPB + tid] = pf;
        skm[c * TPB + tid] = pk;
    }
    __syncthreads();

    for (int it = 0; it < NEWTON_ITERS; it++) {
        float acc[NMON];
#pragma unroll
        for (int m = 0; m < NMON; m++) acc[m] = 0.0f;

        // ---- compute phase: LDS + FMA only (no global, no masks) ----
#pragma unroll
        for (int c = 0; c < CHUNKS; c++) {
            float4 ff = sfm[c * TPB + tid];
            float4 kk = skm[c * TPB + tid];
            float fa[4] = {ff.x, ff.y, ff.z, ff.w};
            float ka[4] = {kk.x, kk.y, kk.z, kk.w};
#pragma unroll
            for (int j = 0; j < 4; j++) {
                float uu = u[c * 4 + j];
                float u2 = uu * uu;
                float t  = fmaf(0.4f, u2, ka[j]);
                float g  = fmaf(-uu, t, fa[j]);
                float h  = fmaf(1.2f, u2, ka[j]);
                float v  = -g * frcp_approx(h);
                du[c * 4 + j] = v;
                float v2 = v * v;
                float P  = uu * v2;
                float Q  = v * v2;
                acc[0] = fmaf(g, g, acc[0]);
                acc[1] = fmaf(P, P, acc[1]);
                acc[2] = fmaf(Q, Q, acc[2]);
                acc[3] = fmaf(g, P, acc[3]);
                acc[4] = fmaf(g, Q, acc[4]);
                acc[5] = fmaf(P, Q, acc[5]);
            }
        }

        // ---- warp shuffle reduce, stage per-warp sums ----
#pragma unroll
        for (int m = 0; m < NMON; m++) {
#pragma unroll
            for (int o = 16; o; o >>= 1)
                acc[m] += __shfl_down_sync(0xffffffffu, acc[m], o);
        }
        if (lane == 0) {
#pragma unroll
            for (int m = 0; m < NMON; m++) sred[wid * NMON + m] = acc[m];
        }
        __syncthreads();   // sync 1

        const int buf = it % 3;
        if (wid == 0) {
            // cross-warp reduce: lane w holds warp w's sums
            float s[NMON];
#pragma unroll
            for (int m = 0; m < NMON; m++) s[m] = sred[lane * NMON + m];
#pragma unroll
            for (int o = 16; o; o >>= 1) {
#pragma unroll
                for (int m = 0; m < NMON; m++)
                    s[m] += __shfl_down_sync(0xffffffffu, s[m], o);
            }
            if (lane == 0) {
#pragma unroll
                for (int m = 0; m < NMON; m++)
                    redAddRelaxedF32(&g_sum[buf][m * BATCH + b], s[m]);
                // release-arrive covers the red.adds above (program order)
                redAddReleaseS32(&g_cnt[it][b], 1);
                while (ldAcquireS32(&g_cnt[it][b]) < BX) __nanosleep(64);

                // alpha from the 6 global sums (quadratic form per trial)
                const float* S = &g_sum[buf][0];
                float gg = __ldcg(&S[0 * BATCH + b]);
                float pp = __ldcg(&S[1 * BATCH + b]);
                float qq = __ldcg(&S[2 * BATCH + b]);
                float gp = __ldcg(&S[3 * BATCH + b]);
                float gq = __ldcg(&S[4 * BATCH + b]);
                float pq = __ldcg(&S[5 * BATCH + b]);
                float a = 0.05f;                 // ALPHA_MIN
#pragma unroll
                for (int tr = 7; tr >= 0; tr--) {
                    float at = c_alpha[tr];
                    float c1 = 1.0f + at;
                    float c2 = -1.2f * at * at;
                    float c3 = -0.4f * at * at * at;
                    float n2 = c1 * c1 * gg + c2 * c2 * pp + c3 * c3 * qq
                             + 2.0f * (c1 * c2 * gp + c1 * c3 * gq + c2 * c3 * pq);
                    if (n2 < gg) a = at;         // downward scan -> first improving
                }
                *s_alp = a;

                // bx0 housekeeping: reset old counter, zero the it+2 sum
                // buffer. Release-ordered by bx0's arrival at barrier it+1.
                if (bx == 0) {
                    int prev = (it == 0) ? (NEWTON_ITERS - 1) : (it - 1);
                    __stcg(&g_cnt[prev][b], 0);
                    float* z = &g_sum[(it + 2) % 3][0];
#pragma unroll
                    for (int m = 0; m < NMON; m++) __stcg(&z[m * BATCH + b], 0.0f);
                }
            }
        }
        __syncthreads();   // sync 2

        // ---- update: u += alpha * du ----
        float aB = *s_alp;
#pragma unroll
        for (int x = 0; x < NV; x++)
            u[x] = fmaf(aB, du[x], u[x]);
    }

    // ---- final store: restore u0 at fixed lanes, skip padded tails ----
    float4* o4 = reinterpret_cast<float4*>(out) + (size_t)b * D4;
#pragma unroll
    for (int c = 0; c < CHUNKS; c++) {
        int i = i0 + c * STRIDE;
        if (i < D4) {
            uint32_t nb = (nibs >> (c * 4)) & 0xFu;
            float4 uu = u4[i];
            float4 o;
            o.x = (nb & 1u) ? uu.x : u[c * 4 + 0];
            o.y = (nb & 2u) ? uu.y : u[c * 4 + 1];
            o.z = (nb & 4u) ? uu.z : u[c * 4 + 2];
            o.w = (nb & 8u) ? uu.w : u[c * 4 + 3];
            o4[i] = o;
        }
    }
}

// ---------------------------------------------------------------------------
extern "C" void kernel_launch(void* const* d_in, const int* in_sizes, int n_in,
                              void* d_out, int out_size)
{
    const float* f  = (const float*)d_in[0];   // external_forces [B, DOF]
    const float* u0 = (const float*)d_in[1];   // u0              [B, DOF]
    const float* kd = (const float*)d_in[2];   // k_diag          [DOF]
    const int*   fd = (const int*)d_in[3];     // fixed_dofs      [NFIX]

    const size_t smem = (size_t)CHUNKS * TPB * 16 * 2        // sfm + skm (128KB)
                      + (size_t)CHUNKS * (TPB / 8) * 4       // maskw
                      + (size_t)NWARP * NMON * 4             // sred
                      + 16;                                  // s_alpha + pad
    static int configured = 0;
    if (!configured) {
        cudaFuncSetAttribute(kSolve, cudaFuncAttributeMaxDynamicSharedMemorySize,
                             (int)smem);
        configured = 1;
    }
    kSolve<<<dim3(BX, BATCH), TPB, smem>>>(f, u0, kd, fd, (float*)d_out);
}